// round 16
// baseline (speedup 1.0000x reference)
#include <cuda_runtime.h>
#include <math.h>

#define CB 8
#define CN 16384
#define CC 192
#define C3 576
#define HD 24
#define IMG 128

// ---- scratch (device globals; allocations are forbidden) ----
__device__ float g_qkv[CB * C3 * CN];          // (b, j, n): j<192 q, 192..383 k, 384..575 v
__device__ float g_att[CB * CC * CN];          // att branch -> combined activation
__device__ float g_conv[CB * CC * CN];         // conv branch
__device__ float g_rnorm[CB * 2 * CC];         // reciprocal L2 norms (q rows, then k rows)
__device__ float g_attn_raw[CB * 8 * HD * HD];
__device__ float g_attn[CB * 8 * HD * HD];
__device__ float g_pooled[CB * CC];
__device__ float g_chgate[CB * CC];
__device__ float g_spgate[CB * CN];

__device__ __forceinline__ float geluf(float v) {
    return 0.5f * v * (1.0f + erff(v * 0.70710678118654752440f));
}
__device__ __forceinline__ float sigmoidf(float v) { return 1.0f / (1.0f + expf(-v)); }

__global__ void k_zero() {
    int i = blockIdx.x * 256 + threadIdx.x;
    if (i < CB * 8 * HD * HD) g_attn_raw[i] = 0.f;
}

// ---- K1: qkv GEMM: g_qkv[b][j][n] = sum_c x[b][n][c] * w_qkv[c][j] ----
__global__ __launch_bounds__(256) void k_qkv(const float* __restrict__ x,
                                             const float* __restrict__ w) {
    __shared__ float As[16][132];
    __shared__ float Ws[16][192];
    const int b = blockIdx.z, n0 = blockIdx.x * 128, j0 = blockIdx.y * 192;
    const int tid = threadIdx.x, tn = tid & 15, tj = tid >> 4;
    float acc[8][12];
#pragma unroll
    for (int i = 0; i < 8; i++)
#pragma unroll
        for (int j = 0; j < 12; j++) acc[i][j] = 0.f;
    const float* xb = x + ((size_t)b * CN + n0) * CC;
    for (int k0 = 0; k0 < CC; k0 += 16) {
#pragma unroll
        for (int r = 0; r < 2; r++) {
            int idx = tid + r * 256;
            int n = idx >> 2, q = idx & 3;
            float4 v = *reinterpret_cast<const float4*>(xb + (size_t)n * CC + k0 + q * 4);
            As[q * 4 + 0][n] = v.x; As[q * 4 + 1][n] = v.y;
            As[q * 4 + 2][n] = v.z; As[q * 4 + 3][n] = v.w;
        }
#pragma unroll
        for (int r = 0; r < 12; r++) {
            int idx = tid + r * 256;
            int kk = idx / 192, j = idx - kk * 192;
            Ws[kk][j] = w[(size_t)(k0 + kk) * C3 + j0 + j];
        }
        __syncthreads();
#pragma unroll
        for (int kk = 0; kk < 16; kk++) {
            float a[8], bb[12];
#pragma unroll
            for (int i = 0; i < 8; i++) a[i] = As[kk][tn + 16 * i];
#pragma unroll
            for (int j = 0; j < 12; j++) bb[j] = Ws[kk][tj + 16 * j];
#pragma unroll
            for (int i = 0; i < 8; i++)
#pragma unroll
                for (int j = 0; j < 12; j++) acc[i][j] = fmaf(a[i], bb[j], acc[i][j]);
        }
        __syncthreads();
    }
    float* ob = g_qkv + ((size_t)b * C3 + j0) * CN + n0;
#pragma unroll
    for (int j = 0; j < 12; j++) {
        float* row = ob + (size_t)(tj + 16 * j) * CN;
#pragma unroll
        for (int i = 0; i < 8; i++) row[tn + 16 * i] = acc[i][j];
    }
}

// ---- K2: reciprocal L2 norm over N for each q/k row ----
__global__ __launch_bounds__(256) void k_norm() {
    const int j = blockIdx.x, b = blockIdx.y;
    const float* row = g_qkv + ((size_t)b * C3 + j) * CN;
    float s = 0.f;
    for (int n = threadIdx.x; n < CN; n += 256) { float v = row[n]; s = fmaf(v, v, s); }
    __shared__ float red[8];
#pragma unroll
    for (int o = 16; o; o >>= 1) s += __shfl_down_sync(0xffffffffu, s, o);
    if ((threadIdx.x & 31) == 0) red[threadIdx.x >> 5] = s;
    __syncthreads();
    if (threadIdx.x == 0) {
        float t = 0.f;
#pragma unroll
        for (int w = 0; w < 8; w++) t += red[w];
        g_rnorm[b * (2 * CC) + j] = 1.0f / fmaxf(sqrtf(t), 1e-12f);
    }
}

// ---- K3: attn logits q.k^T over N, split-N x8 with atomic accumulate ----
__global__ __launch_bounds__(256) void k_attn() {
    __shared__ float Qs[128 * 25];
    __shared__ float Ks[128 * 25];
    const int bh = blockIdx.x, b = bh >> 3, h = bh & 7;
    const int n0 = blockIdx.y * 2048, tid = threadIdx.x;
    const float* qbase = g_qkv + ((size_t)b * C3 + h * HD) * CN;
    const float* kbase = qbase + (size_t)CC * CN;
    float acc[3][3];
#pragma unroll
    for (int i = 0; i < 3; i++)
#pragma unroll
        for (int j = 0; j < 3; j++) acc[i][j] = 0.f;
    const int e0 = (tid >> 3) * 3, f0 = (tid & 7) * 3;
    for (int it = 0; it < 16; it++) {
        int nb = n0 + it * 128;
#pragma unroll
        for (int r = 0; r < 12; r++) {
            int idx = tid + r * 256;
            int e = idx >> 7, t = idx & 127;
            Qs[t * 25 + e] = qbase[(size_t)e * CN + nb + t];
            Ks[t * 25 + e] = kbase[(size_t)e * CN + nb + t];
        }
        __syncthreads();
        if (tid < 64) {
#pragma unroll 8
            for (int t = 0; t < 128; t++) {
                float q0 = Qs[t * 25 + e0], q1 = Qs[t * 25 + e0 + 1], q2 = Qs[t * 25 + e0 + 2];
                float k0 = Ks[t * 25 + f0], k1 = Ks[t * 25 + f0 + 1], k2 = Ks[t * 25 + f0 + 2];
                acc[0][0] = fmaf(q0, k0, acc[0][0]); acc[0][1] = fmaf(q0, k1, acc[0][1]); acc[0][2] = fmaf(q0, k2, acc[0][2]);
                acc[1][0] = fmaf(q1, k0, acc[1][0]); acc[1][1] = fmaf(q1, k1, acc[1][1]); acc[1][2] = fmaf(q1, k2, acc[1][2]);
                acc[2][0] = fmaf(q2, k0, acc[2][0]); acc[2][1] = fmaf(q2, k1, acc[2][1]); acc[2][2] = fmaf(q2, k2, acc[2][2]);
            }
        }
        __syncthreads();
    }
    if (tid < 64) {
#pragma unroll
        for (int i = 0; i < 3; i++)
#pragma unroll
            for (int j = 0; j < 3; j++)
                atomicAdd(&g_attn_raw[((size_t)bh * HD + e0 + i) * HD + f0 + j], acc[i][j]);
    }
}

// ---- K3b: apply norms + temperature, softmax over f ----
__global__ void k_attn_fin(const float* __restrict__ temperature) {
    const int bh = blockIdx.x, b = bh >> 3, h = bh & 7;
    const int e = threadIdx.x;
    if (e >= HD) return;
    const float rq = g_rnorm[b * (2 * CC) + h * HD + e];
    const float tmp = temperature[h];
    float vals[HD], m = -1e30f;
#pragma unroll
    for (int f = 0; f < HD; f++) {
        float rk = g_rnorm[b * (2 * CC) + CC + h * HD + f];
        float v = g_attn_raw[((size_t)bh * HD + e) * HD + f] * rq * rk * tmp;
        vals[f] = v; m = fmaxf(m, v);
    }
    float s = 0.f;
#pragma unroll
    for (int f = 0; f < HD; f++) { vals[f] = expf(vals[f] - m); s += vals[f]; }
    float inv = 1.f / s;
#pragma unroll
    for (int f = 0; f < HD; f++) g_attn[((size_t)bh * HD + e) * HD + f] = vals[f] * inv;
}

// ---- K4: att = attn @ v ----
__global__ __launch_bounds__(256) void k_attx() {
    __shared__ float A[HD * HD];
    const int bh = blockIdx.x, b = bh >> 3, h = bh & 7;
    const int n0 = blockIdx.y * 2048, tid = threadIdx.x;
    for (int i = tid; i < HD * HD; i += 256) A[i] = g_attn[(size_t)bh * HD * HD + i];
    __syncthreads();
    const float* vbase = g_qkv + ((size_t)b * C3 + 2 * CC + h * HD) * CN;
    float* obase = g_att + ((size_t)b * CC + h * HD) * CN;
    for (int it = 0; it < 4; it++) {
        int na = n0 + it * 512 + tid, nb = na + 256;
        float v0[HD], v1[HD];
#pragma unroll
        for (int f = 0; f < HD; f++) {
            v0[f] = vbase[(size_t)f * CN + na];
            v1[f] = vbase[(size_t)f * CN + nb];
        }
#pragma unroll
        for (int e = 0; e < HD; e++) {
            float s0 = 0.f, s1 = 0.f;
#pragma unroll
            for (int f = 0; f < HD; f++) {
                float a = A[e * HD + f];
                s0 = fmaf(a, v0[f], s0); s1 = fmaf(a, v1[f], s1);
            }
            obase[(size_t)e * CN + na] = s0;
            obase[(size_t)e * CN + nb] = s1;
        }
    }
}

// ---- K4b: per-(b,c) mean of att branch ----
__global__ __launch_bounds__(256) void k_pool() {
    const int c = blockIdx.x, b = blockIdx.y;
    const float* row = g_att + ((size_t)b * CC + c) * CN;
    float s = 0.f;
    for (int n = threadIdx.x; n < CN; n += 256) s += row[n];
    __shared__ float red[8];
#pragma unroll
    for (int o = 16; o; o >>= 1) s += __shfl_down_sync(0xffffffffu, s, o);
    if ((threadIdx.x & 31) == 0) red[threadIdx.x >> 5] = s;
    __syncthreads();
    if (threadIdx.x == 0) {
        float t = 0.f;
#pragma unroll
        for (int w = 0; w < 8; w++) t += red[w];
        g_pooled[b * CC + c] = t * (1.0f / (float)CN);
    }
}

// ---- K5: depthwise 3x3 + BN1 + GELU on v image ----
__global__ __launch_bounds__(256) void k_conv(const float* __restrict__ dw_w, const float* __restrict__ dw_b,
                                              const float* __restrict__ g1, const float* __restrict__ b1,
                                              const float* __restrict__ m1, const float* __restrict__ v1) {
    const int bc = blockIdx.y, b = bc / CC, c = bc - b * CC;
    const int tile = blockIdx.x;
    const int y = (tile >> 3) * 16 + (threadIdx.x >> 4);
    const int x = (tile & 7) * 16 + (threadIdx.x & 15);
    const float* v = g_qkv + ((size_t)b * C3 + 2 * CC + c) * CN;
    float w9[9];
#pragma unroll
    for (int i = 0; i < 9; i++) w9[i] = dw_w[c * 9 + i];
    float s = 0.f;
#pragma unroll
    for (int dy = 0; dy < 3; dy++) {
        int yy = y + dy - 1;
        if (yy < 0 || yy >= IMG) continue;
#pragma unroll
        for (int dx = 0; dx < 3; dx++) {
            int xx = x + dx - 1;
            if (xx < 0 || xx >= IMG) continue;
            s = fmaf(v[yy * IMG + xx], w9[dy * 3 + dx], s);
        }
    }
    s += dw_b[c];
    float inv = g1[c] * rsqrtf(v1[c] + 1e-5f);
    s = s * inv + (b1[c] - m1[c] * inv);
    g_conv[((size_t)b * CC + c) * CN + y * IMG + x] = geluf(s);
}

// ---- K6a: channel SE gate ----
__global__ void k_chgate(const float* __restrict__ ci_w1, const float* __restrict__ ci_b1,
                         const float* __restrict__ g2, const float* __restrict__ b2,
                         const float* __restrict__ m2, const float* __restrict__ v2,
                         const float* __restrict__ ci_w2, const float* __restrict__ ci_b2) {
    __shared__ float ps[CC];
    __shared__ float cms[HD];
    const int b = blockIdx.x, t = threadIdx.x;
    ps[t] = g_pooled[b * CC + t];
    __syncthreads();
    if (t < HD) {
        float s = ci_b1[t];
        for (int c = 0; c < CC; c++) s = fmaf(ps[c], ci_w1[t * CC + c], s);
        float inv = g2[t] * rsqrtf(v2[t] + 1e-5f);
        s = s * inv + (b2[t] - m2[t] * inv);
        cms[t] = geluf(s);
    }
    __syncthreads();
    float s = ci_b2[t];
#pragma unroll
    for (int o = 0; o < HD; o++) s = fmaf(cms[o], ci_w2[t * HD + o], s);
    g_chgate[b * CC + t] = sigmoidf(s);
}

// ---- K6b: spatial gate per token ----
__global__ __launch_bounds__(256) void k_spgate(const float* __restrict__ si_w1, const float* __restrict__ si_b1,
                                                const float* __restrict__ g3, const float* __restrict__ b3,
                                                const float* __restrict__ m3, const float* __restrict__ v3,
                                                const float* __restrict__ si_w2, const float* __restrict__ si_b2) {
    __shared__ float Ws[12 * CC];
    const int b = blockIdx.y, n = blockIdx.x * 256 + threadIdx.x;
    for (int i = threadIdx.x; i < 12 * CC; i += 256) Ws[i] = si_w1[i];
    __syncthreads();
    const float* cb = g_conv + (size_t)b * CC * CN + n;
    float a[12];
#pragma unroll
    for (int o = 0; o < 12; o++) a[o] = 0.f;
    for (int c = 0; c < CC; c++) {
        float cv = cb[(size_t)c * CN];
#pragma unroll
        for (int o = 0; o < 12; o++) a[o] = fmaf(Ws[o * CC + c], cv, a[o]);
    }
    float s = si_b2[0];
#pragma unroll
    for (int o = 0; o < 12; o++) {
        float inv = g3[o] * rsqrtf(v3[o] + 1e-5f);
        float val = geluf((a[o] + si_b1[o]) * inv + (b3[o] - m3[o] * inv));
        s = fmaf(val, si_w2[o], s);
    }
    g_spgate[b * CN + n] = sigmoidf(s);
}

// ---- K6c: cross gating combine (in place into g_att) ----
__global__ __launch_bounds__(256) void k_combine() {
    const size_t idx = (size_t)blockIdx.x * 256 + threadIdx.x;   // float4 index
    const int nq = (int)(idx & 4095);
    const int c = (int)((idx >> 12) % CC);
    const int b = (int)(idx / ((size_t)4096 * CC));
    float4 av = reinterpret_cast<float4*>(g_att)[idx];
    float4 cv = reinterpret_cast<const float4*>(g_conv)[idx];
    float4 sp = reinterpret_cast<const float4*>(g_spgate)[(size_t)b * 4096 + nq];
    float ch = g_chgate[b * CC + c];
    av.x = av.x * sp.x + cv.x * ch;
    av.y = av.y * sp.y + cv.y * ch;
    av.z = av.z * sp.z + cv.z * ch;
    av.w = av.w * sp.w + cv.w * ch;
    reinterpret_cast<float4*>(g_att)[idx] = av;
}

// ---- K7: out[b,n,o] = sum_c comb[b,c,n] * proj_w[c,o] + proj_b[o] ----
__global__ __launch_bounds__(256) void k_proj(const float* __restrict__ pw,
                                              const float* __restrict__ pb,
                                              float* __restrict__ out) {
    __shared__ float As[16][128];
    __shared__ float Ws[16][192];
    const int b = blockIdx.z, n0 = blockIdx.x * 128;
    const int tid = threadIdx.x, to = tid & 15, tn = tid >> 4;
    float acc[8][12];
#pragma unroll
    for (int i = 0; i < 8; i++)
#pragma unroll
        for (int j = 0; j < 12; j++) acc[i][j] = 0.f;
    const float* ab = g_att + (size_t)b * CC * CN + n0;
    for (int c0 = 0; c0 < CC; c0 += 16) {
#pragma unroll
        for (int r = 0; r < 2; r++) {
            int idx = tid + r * 256;
            int kk = idx >> 5, nq = idx & 31;
            float4 v = *reinterpret_cast<const float4*>(ab + (size_t)(c0 + kk) * CN + nq * 4);
            *reinterpret_cast<float4*>(&As[kk][nq * 4]) = v;
        }
#pragma unroll
        for (int r = 0; r < 12; r++) {
            int idx = tid + r * 256;
            int kk = idx / 192, o = idx - kk * 192;
            Ws[kk][o] = pw[(size_t)(c0 + kk) * CC + o];
        }
        __syncthreads();
#pragma unroll
        for (int kk = 0; kk < 16; kk++) {
            float a[8], bb[12];
#pragma unroll
            for (int i = 0; i < 8; i++) a[i] = As[kk][tn + 16 * i];
#pragma unroll
            for (int j = 0; j < 12; j++) bb[j] = Ws[kk][to + 16 * j];
#pragma unroll
            for (int i = 0; i < 8; i++)
#pragma unroll
                for (int j = 0; j < 12; j++) acc[i][j] = fmaf(a[i], bb[j], acc[i][j]);
        }
        __syncthreads();
    }
    float bias[12];
#pragma unroll
    for (int j = 0; j < 12; j++) bias[j] = pb[to + 16 * j];
#pragma unroll
    for (int i = 0; i < 8; i++) {
        float* row = out + ((size_t)b * CN + n0 + tn + 16 * i) * CC;
#pragma unroll
        for (int j = 0; j < 12; j++) row[to + 16 * j] = acc[i][j] + bias[j];
    }
}

extern "C" void kernel_launch(void* const* d_in, const int* in_sizes, int n_in,
                              void* d_out, int out_size) {
    const float* x    = (const float*)d_in[0];
    const float* wqkv = (const float*)d_in[3];
    const float* temp = (const float*)d_in[4];
    const float* dww  = (const float*)d_in[5];
    const float* dwb  = (const float*)d_in[6];
    const float* b1g  = (const float*)d_in[7];
    const float* b1b  = (const float*)d_in[8];
    const float* b1m  = (const float*)d_in[9];
    const float* b1v  = (const float*)d_in[10];
    const float* ciw1 = (const float*)d_in[11];
    const float* cib1 = (const float*)d_in[12];
    const float* b2g  = (const float*)d_in[13];
    const float* b2b  = (const float*)d_in[14];
    const float* b2m  = (const float*)d_in[15];
    const float* b2v  = (const float*)d_in[16];
    const float* ciw2 = (const float*)d_in[17];
    const float* cib2 = (const float*)d_in[18];
    const float* siw1 = (const float*)d_in[19];
    const float* sib1 = (const float*)d_in[20];
    const float* b3g  = (const float*)d_in[21];
    const float* b3b  = (const float*)d_in[22];
    const float* b3m  = (const float*)d_in[23];
    const float* b3v  = (const float*)d_in[24];
    const float* siw2 = (const float*)d_in[25];
    const float* sib2 = (const float*)d_in[26];
    const float* pw   = (const float*)d_in[27];
    const float* pb   = (const float*)d_in[28];
    float* out = (float*)d_out;

    k_zero<<<144, 256>>>();
    k_qkv<<<dim3(CN / 128, 3, CB), 256>>>(x, wqkv);
    k_norm<<<dim3(2 * CC, CB), 256>>>();
    k_attn<<<dim3(CB * 8, 8), 256>>>();
    k_attn_fin<<<CB * 8, 32>>>(temp);
    k_attx<<<dim3(CB * 8, 8), 256>>>();
    k_pool<<<dim3(CC, CB), 256>>>();
    k_conv<<<dim3(64, CB * CC), 256>>>(dww, dwb, b1g, b1b, b1m, b1v);
    k_chgate<<<CB, CC>>>(ciw1, cib1, b2g, b2b, b2m, b2v, ciw2, cib2);
    k_spgate<<<dim3(CN / 256, CB), 256>>>(siw1, sib1, b3g, b3b, b3m, b3v, siw2, sib2);
    k_combine<<<(CB * CC * CN / 4) / 256, 256>>>();
    k_proj<<<dim3(CN / 128, 1, CB), 256>>>(pw, pb, out);
}

// round 17
// speedup vs baseline: 1.3865x; 1.3865x over previous
#include <cuda_runtime.h>
#include <math.h>
#include <stdint.h>

#define CB 8
#define CN 16384
#define CC 192
#define C3 576
#define HD 24
#define IMG 128

// ---- scratch (device globals; allocations are forbidden) ----
__device__ float g_qkv[CB * C3 * CN];          // (b, j, n): j<192 q, 192..383 k, 384..575 v
__device__ float g_att[CB * CC * CN];          // att branch -> combined activation
__device__ float g_conv[CB * CC * CN];         // conv branch
__device__ float g_rnorm[CB * 2 * CC];         // reciprocal L2 norms (q rows, then k rows)
__device__ float g_attn_raw[CB * 8 * HD * HD];
__device__ float g_attn[CB * 8 * HD * HD];
__device__ float g_pooled[CB * CC];
__device__ float g_chgate[CB * CC];
__device__ float g_spgate[CB * CN];

__device__ __forceinline__ float geluf(float v) {
    return 0.5f * v * (1.0f + erff(v * 0.70710678118654752440f));
}
__device__ __forceinline__ float sigmoidf(float v) { return 1.0f / (1.0f + expf(-v)); }

__device__ __forceinline__ uint32_t f2tf(float f) {
    uint32_t u;
    asm("cvt.rna.tf32.f32 %0, %1;" : "=r"(u) : "f"(f));
    return u;
}
__device__ __forceinline__ void mma8(float* d, const uint32_t* a, const uint32_t* b) {
    asm volatile(
        "mma.sync.aligned.m16n8k8.row.col.f32.tf32.tf32.f32 "
        "{%0,%1,%2,%3},{%4,%5,%6,%7},{%8,%9},{%0,%1,%2,%3};"
        : "+f"(d[0]), "+f"(d[1]), "+f"(d[2]), "+f"(d[3])
        : "r"(a[0]), "r"(a[1]), "r"(a[2]), "r"(a[3]), "r"(b[0]), "r"(b[1]));
}

__global__ void k_zero() {
    int i = blockIdx.x * 256 + threadIdx.x;
    if (i < CB * 8 * HD * HD) g_attn_raw[i] = 0.f;
}

// ---- K1 (tensor core): g_qkv[b][j][n] = sum_c x[b][n][c] * w_qkv[c][j] ----
// block tile: 64 j x 128 n, K-chunks of 16; warps 2(M) x 4(N), warp tile 32x32.
__global__ __launch_bounds__(256) void k_qkv_tc(const float* __restrict__ x,
                                                const float* __restrict__ w) {
    __shared__ uint32_t Wt[16][68];    // [c][j]
    __shared__ uint32_t Xt[16][132];   // [c][n]
    const int b = blockIdx.z, n0 = blockIdx.x * 128, j0 = blockIdx.y * 64;
    const int tid = threadIdx.x, warp = tid >> 5, lane = tid & 31;
    const int g = lane >> 2, lc = lane & 3;
    const int wm = warp >> 2, wn = warp & 3;      // wm: 0..1, wn: 0..3
    const int jb = wm * 32, nb = wn * 32;

    float acc[2][4][4];
#pragma unroll
    for (int mt = 0; mt < 2; mt++)
#pragma unroll
        for (int nt = 0; nt < 4; nt++)
#pragma unroll
            for (int r = 0; r < 4; r++) acc[mt][nt][r] = 0.f;

    const float* xb = x + ((size_t)b * CN + n0) * CC;
    for (int k0 = 0; k0 < CC; k0 += 16) {
        {   // W tile: 16c x 64j -> 256 float4, one per thread
            int c = tid >> 4, jq = tid & 15;
            float4 v = *reinterpret_cast<const float4*>(w + (size_t)(k0 + c) * C3 + j0 + jq * 4);
            Wt[c][jq * 4 + 0] = f2tf(v.x); Wt[c][jq * 4 + 1] = f2tf(v.y);
            Wt[c][jq * 4 + 2] = f2tf(v.z); Wt[c][jq * 4 + 3] = f2tf(v.w);
        }
#pragma unroll
        for (int r = 0; r < 2; r++) {   // X tile: 128n x 16c
            int idx = tid + r * 256;
            int n = idx >> 2, q = idx & 3;
            float4 v = *reinterpret_cast<const float4*>(xb + (size_t)n * CC + k0 + q * 4);
            Xt[q * 4 + 0][n] = f2tf(v.x); Xt[q * 4 + 1][n] = f2tf(v.y);
            Xt[q * 4 + 2][n] = f2tf(v.z); Xt[q * 4 + 3][n] = f2tf(v.w);
        }
        __syncthreads();
#pragma unroll
        for (int kk = 0; kk < 16; kk += 8) {
            uint32_t a[2][4], bf[4][2];
#pragma unroll
            for (int mt = 0; mt < 2; mt++) {
                int j = jb + mt * 16 + g;
                a[mt][0] = Wt[kk + lc][j];
                a[mt][1] = Wt[kk + lc][j + 8];
                a[mt][2] = Wt[kk + lc + 4][j];
                a[mt][3] = Wt[kk + lc + 4][j + 8];
            }
#pragma unroll
            for (int nt = 0; nt < 4; nt++) {
                int n = nb + nt * 8 + g;
                bf[nt][0] = Xt[kk + lc][n];
                bf[nt][1] = Xt[kk + lc + 4][n];
            }
#pragma unroll
            for (int mt = 0; mt < 2; mt++)
#pragma unroll
                for (int nt = 0; nt < 4; nt++) mma8(acc[mt][nt], a[mt], bf[nt]);
        }
        __syncthreads();
    }
#pragma unroll
    for (int mt = 0; mt < 2; mt++) {
        int j = j0 + jb + mt * 16 + g;
        float* row0 = g_qkv + ((size_t)b * C3 + j) * CN + n0;
        float* row1 = row0 + (size_t)8 * CN;
#pragma unroll
        for (int nt = 0; nt < 4; nt++) {
            int n = nb + nt * 8 + lc * 2;
            *reinterpret_cast<float2*>(row0 + n) = make_float2(acc[mt][nt][0], acc[mt][nt][1]);
            *reinterpret_cast<float2*>(row1 + n) = make_float2(acc[mt][nt][2], acc[mt][nt][3]);
        }
    }
}

// ---- K2: reciprocal L2 norm over N for each q/k row ----
__global__ __launch_bounds__(256) void k_norm() {
    const int j = blockIdx.x, b = blockIdx.y;
    const float* row = g_qkv + ((size_t)b * C3 + j) * CN;
    float s = 0.f;
    for (int n = threadIdx.x; n < CN; n += 256) { float v = row[n]; s = fmaf(v, v, s); }
    __shared__ float red[8];
#pragma unroll
    for (int o = 16; o; o >>= 1) s += __shfl_down_sync(0xffffffffu, s, o);
    if ((threadIdx.x & 31) == 0) red[threadIdx.x >> 5] = s;
    __syncthreads();
    if (threadIdx.x == 0) {
        float t = 0.f;
#pragma unroll
        for (int w = 0; w < 8; w++) t += red[w];
        g_rnorm[b * (2 * CC) + j] = 1.0f / fmaxf(sqrtf(t), 1e-12f);
    }
}

// ---- K3: attn logits q.k^T over N, split-N x8 with atomic accumulate ----
__global__ __launch_bounds__(256) void k_attn() {
    __shared__ float Qs[128 * 25];
    __shared__ float Ks[128 * 25];
    const int bh = blockIdx.x, b = bh >> 3, h = bh & 7;
    const int n0 = blockIdx.y * 2048, tid = threadIdx.x;
    const float* qbase = g_qkv + ((size_t)b * C3 + h * HD) * CN;
    const float* kbase = qbase + (size_t)CC * CN;
    float acc[3][3];
#pragma unroll
    for (int i = 0; i < 3; i++)
#pragma unroll
        for (int j = 0; j < 3; j++) acc[i][j] = 0.f;
    const int e0 = (tid >> 3) * 3, f0 = (tid & 7) * 3;
    for (int it = 0; it < 16; it++) {
        int nbq = n0 + it * 128;
#pragma unroll
        for (int r = 0; r < 12; r++) {
            int idx = tid + r * 256;
            int e = idx >> 7, t = idx & 127;
            Qs[t * 25 + e] = qbase[(size_t)e * CN + nbq + t];
            Ks[t * 25 + e] = kbase[(size_t)e * CN + nbq + t];
        }
        __syncthreads();
        if (tid < 64) {
#pragma unroll 8
            for (int t = 0; t < 128; t++) {
                float q0 = Qs[t * 25 + e0], q1 = Qs[t * 25 + e0 + 1], q2 = Qs[t * 25 + e0 + 2];
                float k0 = Ks[t * 25 + f0], k1 = Ks[t * 25 + f0 + 1], k2 = Ks[t * 25 + f0 + 2];
                acc[0][0] = fmaf(q0, k0, acc[0][0]); acc[0][1] = fmaf(q0, k1, acc[0][1]); acc[0][2] = fmaf(q0, k2, acc[0][2]);
                acc[1][0] = fmaf(q1, k0, acc[1][0]); acc[1][1] = fmaf(q1, k1, acc[1][1]); acc[1][2] = fmaf(q1, k2, acc[1][2]);
                acc[2][0] = fmaf(q2, k0, acc[2][0]); acc[2][1] = fmaf(q2, k1, acc[2][1]); acc[2][2] = fmaf(q2, k2, acc[2][2]);
            }
        }
        __syncthreads();
    }
    if (tid < 64) {
#pragma unroll
        for (int i = 0; i < 3; i++)
#pragma unroll
            for (int j = 0; j < 3; j++)
                atomicAdd(&g_attn_raw[((size_t)bh * HD + e0 + i) * HD + f0 + j], acc[i][j]);
    }
}

// ---- K3b: apply norms + temperature, softmax over f ----
__global__ void k_attn_fin(const float* __restrict__ temperature) {
    const int bh = blockIdx.x, b = bh >> 3, h = bh & 7;
    const int e = threadIdx.x;
    if (e >= HD) return;
    const float rq = g_rnorm[b * (2 * CC) + h * HD + e];
    const float tmp = temperature[h];
    float vals[HD], m = -1e30f;
#pragma unroll
    for (int f = 0; f < HD; f++) {
        float rk = g_rnorm[b * (2 * CC) + CC + h * HD + f];
        float v = g_attn_raw[((size_t)bh * HD + e) * HD + f] * rq * rk * tmp;
        vals[f] = v; m = fmaxf(m, v);
    }
    float s = 0.f;
#pragma unroll
    for (int f = 0; f < HD; f++) { vals[f] = expf(vals[f] - m); s += vals[f]; }
    float inv = 1.f / s;
#pragma unroll
    for (int f = 0; f < HD; f++) g_attn[((size_t)bh * HD + e) * HD + f] = vals[f] * inv;
}

// ---- K4: att = attn @ v ----
__global__ __launch_bounds__(256) void k_attx() {
    __shared__ float A[HD * HD];
    const int bh = blockIdx.x, b = bh >> 3, h = bh & 7;
    const int n0 = blockIdx.y * 2048, tid = threadIdx.x;
    for (int i = tid; i < HD * HD; i += 256) A[i] = g_attn[(size_t)bh * HD * HD + i];
    __syncthreads();
    const float* vbase = g_qkv + ((size_t)b * C3 + 2 * CC + h * HD) * CN;
    float* obase = g_att + ((size_t)b * CC + h * HD) * CN;
    for (int it = 0; it < 4; it++) {
        int na = n0 + it * 512 + tid, nb2 = na + 256;
        float v0[HD], v1[HD];
#pragma unroll
        for (int f = 0; f < HD; f++) {
            v0[f] = vbase[(size_t)f * CN + na];
            v1[f] = vbase[(size_t)f * CN + nb2];
        }
#pragma unroll
        for (int e = 0; e < HD; e++) {
            float s0 = 0.f, s1 = 0.f;
#pragma unroll
            for (int f = 0; f < HD; f++) {
                float a = A[e * HD + f];
                s0 = fmaf(a, v0[f], s0); s1 = fmaf(a, v1[f], s1);
            }
            obase[(size_t)e * CN + na] = s0;
            obase[(size_t)e * CN + nb2] = s1;
        }
    }
}

// ---- K4b: per-(b,c) mean of att branch ----
__global__ __launch_bounds__(256) void k_pool() {
    const int c = blockIdx.x, b = blockIdx.y;
    const float* row = g_att + ((size_t)b * CC + c) * CN;
    float s = 0.f;
    for (int n = threadIdx.x; n < CN; n += 256) s += row[n];
    __shared__ float red[8];
#pragma unroll
    for (int o = 16; o; o >>= 1) s += __shfl_down_sync(0xffffffffu, s, o);
    if ((threadIdx.x & 31) == 0) red[threadIdx.x >> 5] = s;
    __syncthreads();
    if (threadIdx.x == 0) {
        float t = 0.f;
#pragma unroll
        for (int w = 0; w < 8; w++) t += red[w];
        g_pooled[b * CC + c] = t * (1.0f / (float)CN);
    }
}

// ---- K5: depthwise 3x3 + BN1 + GELU on v image ----
__global__ __launch_bounds__(256) void k_conv(const float* __restrict__ dw_w, const float* __restrict__ dw_b,
                                              const float* __restrict__ g1, const float* __restrict__ b1,
                                              const float* __restrict__ m1, const float* __restrict__ v1) {
    const int bc = blockIdx.y, b = bc / CC, c = bc - b * CC;
    const int tile = blockIdx.x;
    const int y = (tile >> 3) * 16 + (threadIdx.x >> 4);
    const int x = (tile & 7) * 16 + (threadIdx.x & 15);
    const float* v = g_qkv + ((size_t)b * C3 + 2 * CC + c) * CN;
    float w9[9];
#pragma unroll
    for (int i = 0; i < 9; i++) w9[i] = dw_w[c * 9 + i];
    float s = 0.f;
#pragma unroll
    for (int dy = 0; dy < 3; dy++) {
        int yy = y + dy - 1;
        if (yy < 0 || yy >= IMG) continue;
#pragma unroll
        for (int dx = 0; dx < 3; dx++) {
            int xx = x + dx - 1;
            if (xx < 0 || xx >= IMG) continue;
            s = fmaf(v[yy * IMG + xx], w9[dy * 3 + dx], s);
        }
    }
    s += dw_b[c];
    float inv = g1[c] * rsqrtf(v1[c] + 1e-5f);
    s = s * inv + (b1[c] - m1[c] * inv);
    g_conv[((size_t)b * CC + c) * CN + y * IMG + x] = geluf(s);
}

// ---- K6a: channel SE gate ----
__global__ void k_chgate(const float* __restrict__ ci_w1, const float* __restrict__ ci_b1,
                         const float* __restrict__ g2, const float* __restrict__ b2,
                         const float* __restrict__ m2, const float* __restrict__ v2,
                         const float* __restrict__ ci_w2, const float* __restrict__ ci_b2) {
    __shared__ float ps[CC];
    __shared__ float cms[HD];
    const int b = blockIdx.x, t = threadIdx.x;
    ps[t] = g_pooled[b * CC + t];
    __syncthreads();
    if (t < HD) {
        float s = ci_b1[t];
        for (int c = 0; c < CC; c++) s = fmaf(ps[c], ci_w1[t * CC + c], s);
        float inv = g2[t] * rsqrtf(v2[t] + 1e-5f);
        s = s * inv + (b2[t] - m2[t] * inv);
        cms[t] = geluf(s);
    }
    __syncthreads();
    float s = ci_b2[t];
#pragma unroll
    for (int o = 0; o < HD; o++) s = fmaf(cms[o], ci_w2[t * HD + o], s);
    g_chgate[b * CC + t] = sigmoidf(s);
}

// ---- K6b: spatial gate per token ----
__global__ __launch_bounds__(256) void k_spgate(const float* __restrict__ si_w1, const float* __restrict__ si_b1,
                                                const float* __restrict__ g3, const float* __restrict__ b3,
                                                const float* __restrict__ m3, const float* __restrict__ v3,
                                                const float* __restrict__ si_w2, const float* __restrict__ si_b2) {
    __shared__ float Ws[12 * CC];
    const int b = blockIdx.y, n = blockIdx.x * 256 + threadIdx.x;
    for (int i = threadIdx.x; i < 12 * CC; i += 256) Ws[i] = si_w1[i];
    __syncthreads();
    const float* cb = g_conv + (size_t)b * CC * CN + n;
    float a[12];
#pragma unroll
    for (int o = 0; o < 12; o++) a[o] = 0.f;
    for (int c = 0; c < CC; c++) {
        float cv = cb[(size_t)c * CN];
#pragma unroll
        for (int o = 0; o < 12; o++) a[o] = fmaf(Ws[o * CC + c], cv, a[o]);
    }
    float s = si_b2[0];
#pragma unroll
    for (int o = 0; o < 12; o++) {
        float inv = g3[o] * rsqrtf(v3[o] + 1e-5f);
        float val = geluf((a[o] + si_b1[o]) * inv + (b3[o] - m3[o] * inv));
        s = fmaf(val, si_w2[o], s);
    }
    g_spgate[b * CN + n] = sigmoidf(s);
}

// ---- K6c: cross gating combine (in place into g_att) ----
__global__ __launch_bounds__(256) void k_combine() {
    const size_t idx = (size_t)blockIdx.x * 256 + threadIdx.x;   // float4 index
    const int nq = (int)(idx & 4095);
    const int c = (int)((idx >> 12) % CC);
    const int b = (int)(idx / ((size_t)4096 * CC));
    float4 av = reinterpret_cast<float4*>(g_att)[idx];
    float4 cv = reinterpret_cast<const float4*>(g_conv)[idx];
    float4 sp = reinterpret_cast<const float4*>(g_spgate)[(size_t)b * 4096 + nq];
    float ch = g_chgate[b * CC + c];
    av.x = av.x * sp.x + cv.x * ch;
    av.y = av.y * sp.y + cv.y * ch;
    av.z = av.z * sp.z + cv.z * ch;
    av.w = av.w * sp.w + cv.w * ch;
    reinterpret_cast<float4*>(g_att)[idx] = av;
}

// ---- K7 (tensor core): out[b,n,o] = sum_c comb[b,c,n] * proj_w[c,o] + proj_b[o] ----
// block tile: 64 n (M) x 192 o (N); warps 2(M) x 4(N): warp tile 32n x 48o.
__global__ __launch_bounds__(256) void k_proj_tc(const float* __restrict__ pw,
                                                 const float* __restrict__ pb,
                                                 float* __restrict__ out) {
    __shared__ uint32_t At[16][68];    // [c][n]
    __shared__ uint32_t Wt[16][196];   // [c][o]
    const int b = blockIdx.z, n0 = blockIdx.x * 64;
    const int tid = threadIdx.x, warp = tid >> 5, lane = tid & 31;
    const int g = lane >> 2, lc = lane & 3;
    const int wm = warp >> 2, wn = warp & 3;
    const int nb = wm * 32, ob = wn * 48;

    float acc[2][6][4];
#pragma unroll
    for (int mt = 0; mt < 2; mt++)
#pragma unroll
        for (int nt = 0; nt < 6; nt++)
#pragma unroll
            for (int r = 0; r < 4; r++) acc[mt][nt][r] = 0.f;

    const float* ab = g_att + (size_t)b * CC * CN + n0;
    for (int c0 = 0; c0 < CC; c0 += 16) {
        {   // A tile: 16c x 64n
            int c = tid >> 4, nq = tid & 15;
            float4 v = *reinterpret_cast<const float4*>(ab + (size_t)(c0 + c) * CN + nq * 4);
            At[c][nq * 4 + 0] = f2tf(v.x); At[c][nq * 4 + 1] = f2tf(v.y);
            At[c][nq * 4 + 2] = f2tf(v.z); At[c][nq * 4 + 3] = f2tf(v.w);
        }
#pragma unroll
        for (int r = 0; r < 3; r++) {   // W tile: 16c x 192o
            int idx = tid + r * 256;
            int c = idx / 48, oq = idx % 48;
            float4 v = *reinterpret_cast<const float4*>(pw + (size_t)(c0 + c) * CC + oq * 4);
            Wt[c][oq * 4 + 0] = f2tf(v.x); Wt[c][oq * 4 + 1] = f2tf(v.y);
            Wt[c][oq * 4 + 2] = f2tf(v.z); Wt[c][oq * 4 + 3] = f2tf(v.w);
        }
        __syncthreads();
#pragma unroll
        for (int kk = 0; kk < 16; kk += 8) {
            uint32_t a[2][4], bf[6][2];
#pragma unroll
            for (int mt = 0; mt < 2; mt++) {
                int n = nb + mt * 16 + g;
                a[mt][0] = At[kk + lc][n];
                a[mt][1] = At[kk + lc][n + 8];
                a[mt][2] = At[kk + lc + 4][n];
                a[mt][3] = At[kk + lc + 4][n + 8];
            }
#pragma unroll
            for (int nt = 0; nt < 6; nt++) {
                int o = ob + nt * 8 + g;
                bf[nt][0] = Wt[kk + lc][o];
                bf[nt][1] = Wt[kk + lc + 4][o];
            }
#pragma unroll
            for (int mt = 0; mt < 2; mt++)
#pragma unroll
                for (int nt = 0; nt < 6; nt++) mma8(acc[mt][nt], a[mt], bf[nt]);
        }
        __syncthreads();
    }
#pragma unroll
    for (int nt = 0; nt < 6; nt++) {
        int o = ob + nt * 8 + lc * 2;
        float2 bias = make_float2(pb[o], pb[o + 1]);
#pragma unroll
        for (int mt = 0; mt < 2; mt++) {
            int n = n0 + nb + mt * 16 + g;
            float* r0 = out + ((size_t)b * CN + n) * CC + o;
            float* r1 = r0 + (size_t)8 * CC;
            *reinterpret_cast<float2*>(r0) = make_float2(acc[mt][nt][0] + bias.x, acc[mt][nt][1] + bias.y);
            *reinterpret_cast<float2*>(r1) = make_float2(acc[mt][nt][2] + bias.x, acc[mt][nt][3] + bias.y);
        }
    }
}

extern "C" void kernel_launch(void* const* d_in, const int* in_sizes, int n_in,
                              void* d_out, int out_size) {
    const float* x    = (const float*)d_in[0];
    const float* wqkv = (const float*)d_in[3];
    const float* temp = (const float*)d_in[4];
    const float* dww  = (const float*)d_in[5];
    const float* dwb  = (const float*)d_in[6];
    const float* b1g  = (const float*)d_in[7];
    const float* b1b  = (const float*)d_in[8];
    const float* b1m  = (const float*)d_in[9];
    const float* b1v  = (const float*)d_in[10];
    const float* ciw1 = (const float*)d_in[11];
    const float* cib1 = (const float*)d_in[12];
    const float* b2g  = (const float*)d_in[13];
    const float* b2b  = (const float*)d_in[14];
    const float* b2m  = (const float*)d_in[15];
    const float* b2v  = (const float*)d_in[16];
    const float* ciw2 = (const float*)d_in[17];
    const float* cib2 = (const float*)d_in[18];
    const float* siw1 = (const float*)d_in[19];
    const float* sib1 = (const float*)d_in[20];
    const float* b3g  = (const float*)d_in[21];
    const float* b3b  = (const float*)d_in[22];
    const float* b3m  = (const float*)d_in[23];
    const float* b3v  = (const float*)d_in[24];
    const float* siw2 = (const float*)d_in[25];
    const float* sib2 = (const float*)d_in[26];
    const float* pw   = (const float*)d_in[27];
    const float* pb   = (const float*)d_in[28];
    float* out = (float*)d_out;

    k_zero<<<144, 256>>>();
    k_qkv_tc<<<dim3(CN / 128, 9, CB), 256>>>(x, wqkv);
    k_norm<<<dim3(2 * CC, CB), 256>>>();
    k_attn<<<dim3(CB * 8, 8), 256>>>();
    k_attn_fin<<<CB * 8, 32>>>(temp);
    k_attx<<<dim3(CB * 8, 8), 256>>>();
    k_pool<<<dim3(CC, CB), 256>>>();
    k_conv<<<dim3(64, CB * CC), 256>>>(dww, dwb, b1g, b1b, b1m, b1v);
    k_chgate<<<CB, CC>>>(ciw1, cib1, b2g, b2b, b2m, b2v, ciw2, cib2);
    k_spgate<<<dim3(CN / 256, CB), 256>>>(siw1, sib1, b3g, b3b, b3m, b3v, siw2, sib2);
    k_combine<<<(CB * CC * CN / 4) / 256, 256>>>();
    k_proj_tc<<<dim3(CN / 64, 1, CB), 256>>>(pw, pb, out);
}